// round 10
// baseline (speedup 1.0000x reference)
#include <cuda_runtime.h>

#define BB 32
#define TT 128
#define DD 512
#define UU 512
#define G4 2048

// ---------------- scratch (device globals: allocation-free) ----------------
__device__ float g_attx[BB*TT*UU];      // 8 MB   x@W_att + b_att
__device__ float g_xk  [BB*TT*G4];      // 32 MB  x@kernel + bias
__device__ float g_h[2][BB*UU];         // double-buffered hidden state
__device__ float g_c   [BB*UU];
__device__ float g_hU  [BB*UU];
__device__ float g_z   [BB*DD];
__device__ float g_sc  [BB*TT];

__device__ __forceinline__ float my_tanh(float x) {
    x = fminf(fmaxf(x, -15.f), 15.f);
    float e = __expf(2.f * x);
    return __fdividef(e - 1.f, e + 1.f);
}
__device__ __forceinline__ float hsig(float x) {
    return fminf(fmaxf(0.2f * x + 0.5f, 0.f), 1.f);
}

// ---------------- init h0/c0 = 0 (re-run every launch: deterministic) ------
__global__ void k_init() {
    int i = blockIdx.x * 256 + threadIdx.x;
    if (i < BB*UU) { g_h[0][i] = 0.f; g_h[1][i] = 0.f; g_c[i] = 0.f; }
}

// ---------------- precompute: one SGEMM over virtual N = 2048 + 512 --------
// C[m][n]: n<2048 -> g_xk = X@kernel + bias ; n>=2048 -> g_attx = X@W_att + ab
// BM=128, BN=64, BK=16, 256 threads, 8x4 micro-tile (FMA-bound)
__global__ void __launch_bounds__(256) k_pre(
        const float* __restrict__ x, const float* __restrict__ Wk,
        const float* __restrict__ Wa, const float* __restrict__ bias,
        const float* __restrict__ ab) {
    __shared__ float As[16][132];
    __shared__ float Bs[16][64];
    int m0 = blockIdx.y * 128;
    int n0 = blockIdx.x * 64;
    bool isK = (n0 < G4);
    const float* Wm = isK ? Wk : Wa;
    int ldw = isK ? G4 : UU;
    int nc0 = isK ? n0 : (n0 - G4);
    int tid = threadIdx.x;
    int tm = (tid >> 4) * 8;
    int tn = (tid & 15) * 4;
    float acc[8][4];
    #pragma unroll
    for (int i = 0; i < 8; i++)
        #pragma unroll
        for (int j = 0; j < 4; j++) acc[i][j] = 0.f;

    for (int k0 = 0; k0 < DD; k0 += 16) {
        #pragma unroll
        for (int i = 0; i < 2; i++) {
            int idx = tid + i * 256;
            int row = idx >> 2;
            int c4  = (idx & 3) * 4;
            float4 v = *(const float4*)(x + (size_t)(m0 + row) * DD + k0 + c4);
            As[c4+0][row] = v.x; As[c4+1][row] = v.y;
            As[c4+2][row] = v.z; As[c4+3][row] = v.w;
        }
        {
            int row = tid >> 4;
            int c4  = (tid & 15) * 4;
            *(float4*)&Bs[row][c4] =
                *(const float4*)(Wm + (size_t)(k0 + row) * ldw + nc0 + c4);
        }
        __syncthreads();
        #pragma unroll
        for (int kk = 0; kk < 16; kk++) {
            float4 a0 = *(float4*)&As[kk][tm];
            float4 a1 = *(float4*)&As[kk][tm + 4];
            float4 bv = *(float4*)&Bs[kk][tn];
            float am[8] = {a0.x,a0.y,a0.z,a0.w,a1.x,a1.y,a1.z,a1.w};
            float bn[4] = {bv.x,bv.y,bv.z,bv.w};
            #pragma unroll
            for (int i = 0; i < 8; i++)
                #pragma unroll
                for (int j = 0; j < 4; j++)
                    acc[i][j] = fmaf(am[i], bn[j], acc[i][j]);
        }
        __syncthreads();
    }
    const float* bvec = isK ? bias : ab;
    float bj[4];
    #pragma unroll
    for (int j = 0; j < 4; j++) bj[j] = bvec[nc0 + tn + j];
    #pragma unroll
    for (int i = 0; i < 8; i++) {
        int m = m0 + tm + i;
        float* dst = isK ? (g_xk   + (size_t)m * G4 + nc0 + tn)
                         : (g_attx + (size_t)m * UU + nc0 + tn);
        #pragma unroll
        for (int j = 0; j < 4; j++) dst[j] = acc[i][j] + bj[j];
    }
}

// ---------------- per-step: hU = H @ U_att  (grid 64, 8 u-cols/CTA) --------
__global__ void __launch_bounds__(256) k_hU(const float* __restrict__ Ua, int par) {
    __shared__ float h_s[128 * 33];
    __shared__ float Us [128 * 8];
    int u0  = blockIdx.x * 8;
    int tid = threadIdx.x;
    int b   = tid >> 3;
    int ci  = tid & 7;
    const float* hsrc = g_h[par];
    float acc = 0.f;
    for (int kc = 0; kc < 4; kc++) {
        #pragma unroll 4
        for (int i = 0; i < 16; i++) {           // h chunk, transposed [k][b]
            int idx = tid + i * 256;
            int bb = idx >> 7;
            int kk = idx & 127;
            h_s[kk * 33 + bb] = hsrc[bb * UU + kc * 128 + kk];
        }
        {
            int kk = tid >> 1;
            int c4 = (tid & 1) * 4;
            *(float4*)&Us[kk * 8 + c4] =
                *(const float4*)(Ua + (size_t)(kc * 128 + kk) * UU + u0 + c4);
        }
        __syncthreads();
        #pragma unroll 8
        for (int k = 0; k < 128; k++)
            acc = fmaf(h_s[k * 33 + b], Us[k * 8 + ci], acc);
        __syncthreads();
    }
    g_hU[b * UU + u0 + ci] = acc;
}

// ---------------- per-step: scores (grid 128 = 32 b x 4 t-chunks) ----------
__global__ void __launch_bounds__(256) k_scores(const float* __restrict__ V) {
    __shared__ float hU_s[UU];
    __shared__ float V_s [UU];
    int b  = blockIdx.x >> 2;
    int t0 = (blockIdx.x & 3) << 5;
    int tid = threadIdx.x;
    hU_s[tid]       = g_hU[b * UU + tid];
    hU_s[tid + 256] = g_hU[b * UU + tid + 256];
    V_s[tid]        = V[tid];
    V_s[tid + 256]  = V[tid + 256];
    __syncthreads();
    int wid = tid >> 5, lane = tid & 31;
    for (int tt = wid; tt < 32; tt += 8) {
        int t = t0 + tt;
        const float* ax = g_attx + ((size_t)b * TT + t) * UU;
        float p = 0.f;
        #pragma unroll 4
        for (int u = lane; u < UU; u += 32)
            p = fmaf(my_tanh(ax[u] + hU_s[u]), V_s[u], p);
        #pragma unroll
        for (int off = 16; off; off >>= 1)
            p += __shfl_xor_sync(0xffffffffu, p, off);
        if (lane == 0) g_sc[b * TT + t] = p;
    }
}

// ---------------- per-step: softmax over T + z = alpha @ x (grid 32) -------
__global__ void __launch_bounds__(256) k_soft(const float* __restrict__ x) {
    __shared__ float al_s[TT];
    int b = blockIdx.x;
    int tid = threadIdx.x;
    if (tid < 32) {
        float s[4];
        #pragma unroll
        for (int i = 0; i < 4; i++) s[i] = g_sc[b * TT + tid + i * 32];
        float mx = fmaxf(fmaxf(s[0], s[1]), fmaxf(s[2], s[3]));
        #pragma unroll
        for (int off = 16; off; off >>= 1)
            mx = fmaxf(mx, __shfl_xor_sync(0xffffffffu, mx, off));
        float e[4], sum = 0.f;
        #pragma unroll
        for (int i = 0; i < 4; i++) { e[i] = __expf(s[i] - mx); sum += e[i]; }
        #pragma unroll
        for (int off = 16; off; off >>= 1)
            sum += __shfl_xor_sync(0xffffffffu, sum, off);
        float inv = __fdividef(1.f, sum);
        #pragma unroll
        for (int i = 0; i < 4; i++) al_s[tid + i * 32] = e[i] * inv;
    }
    __syncthreads();
    const float* xb = x + (size_t)b * TT * DD;
    float z0 = 0.f, z1 = 0.f;
    int d0 = tid, d1 = tid + 256;
    #pragma unroll 4
    for (int t = 0; t < TT; t++) {
        float a = al_s[t];
        z0 = fmaf(a, xb[t * DD + d0], z0);
        z1 = fmaf(a, xb[t * DD + d1], z1);
    }
    g_z[b * DD + d0] = z0;
    g_z[b * DD + d1] = z1;
}

// ---------------- per-step: gates = xk_t + H@R + Z@A, LSTM update ----------
// grid 128: CTA owns 4 u-indices -> 16 gate cols (i,f,g,o interleaved).
// Dyn SMEM: W_s 1024x16 (64KB) + hz_s 1024x34 (136KB) + gate_s 512 (2KB)
__global__ void __launch_bounds__(256) k_gates(
        const float* __restrict__ R, const float* __restrict__ A,
        float* __restrict__ out, int t, int par) {
    extern __shared__ float sm[];
    float* W_s    = sm;                     // 16384 floats
    float* hz_s   = sm + 16384;             // 34816 floats
    float* gate_s = sm + 16384 + 34816;     // 512 floats
    int u0  = blockIdx.x * 4;
    int tid = threadIdx.x;

    #pragma unroll 8
    for (int i = 0; i < 64; i++) {          // weights [R;A] cols for this tile
        int idx = tid + i * 256;
        int k  = idx >> 4;
        int ci = idx & 15;
        int col = ((ci >> 2) << 9) + u0 + (ci & 3);
        W_s[k * 16 + ci] = (k < 512) ? R[(size_t)k * G4 + col]
                                     : A[(size_t)(k - 512) * G4 + col];
    }
    const float* hsrc = g_h[par];
    #pragma unroll 8
    for (int i = 0; i < 64; i++) {          // h and z, transposed [k][b]
        int idx = tid + i * 256;
        int bb = idx >> 9;
        int kk = idx & 511;
        hz_s[kk * 34 + bb]         = hsrc[idx];
        hz_s[(kk + 512) * 34 + bb] = g_z[idx];
    }
    __syncthreads();

    int bp = tid >> 4;
    int ci = tid & 15;
    int b0 = bp << 1;
    int col = ((ci >> 2) << 9) + u0 + (ci & 3);
    float acc0 = g_xk[((size_t)b0 * TT + t) * G4 + col];
    float acc1 = g_xk[((size_t)(b0 + 1) * TT + t) * G4 + col];
    #pragma unroll 8
    for (int k = 0; k < 1024; k++) {
        float2 hv = *(float2*)&hz_s[k * 34 + b0];
        float w = W_s[k * 16 + ci];
        acc0 = fmaf(hv.x, w, acc0);
        acc1 = fmaf(hv.y, w, acc1);
    }
    gate_s[b0 * 16 + ci]       = acc0;
    gate_s[(b0 + 1) * 16 + ci] = acc1;
    __syncthreads();

    if (tid < 128) {                        // LSTM pointwise for 32 b x 4 u
        int b = tid >> 2;
        int j = tid & 3;
        float gi = hsig(gate_s[b * 16 + 0  + j]);
        float gf = hsig(gate_s[b * 16 + 4  + j]);
        float gg = my_tanh(gate_s[b * 16 + 8  + j]);
        float go = hsig(gate_s[b * 16 + 12 + j]);
        int idx = b * UU + u0 + j;
        float cn = gf * g_c[idx] + gi * gg;
        g_c[idx] = cn;
        float hn = go * my_tanh(cn);
        g_h[par ^ 1][idx] = hn;
        out[((size_t)b * TT + t) * UU + u0 + j] = hn;
    }
}

// ---------------------------------------------------------------------------
extern "C" void kernel_launch(void* const* d_in, const int* in_sizes, int n_in,
                              void* d_out, int out_size) {
    const float* x    = (const float*)d_in[0];
    const float* Wk   = (const float*)d_in[1];  // kernel (D,4U)
    const float* R    = (const float*)d_in[2];  // recurrent_kernel (U,4U)
    const float* A    = (const float*)d_in[3];  // attention_kernel (D,4U)
    const float* Wa   = (const float*)d_in[4];  // attention_W (D,U)
    const float* Ua   = (const float*)d_in[5];  // attention_U (U,U)
    const float* V    = (const float*)d_in[6];  // attention_V (U,1)
    const float* bias = (const float*)d_in[7];  // (4U)
    const float* ab   = (const float*)d_in[8];  // attention_b (U)
    float* out = (float*)d_out;

    const int GATES_SMEM = (16384 + 34816 + 512) * 4;  // 206848 B
    cudaFuncSetAttribute(k_gates, cudaFuncAttributeMaxDynamicSharedMemorySize,
                         GATES_SMEM);

    k_init<<<64, 256>>>();
    k_pre<<<dim3(40, 32), 256>>>(x, Wk, Wa, bias, ab);

    for (int t = 0; t < TT; t++) {
        int par = t & 1;
        k_hU    <<<64, 256>>>(Ua, par);
        k_scores<<<128, 256>>>(V);
        k_soft  <<<32, 256>>>(x);
        k_gates <<<128, 256, GATES_SMEM>>>(R, A, out, t, par);
    }
}

// round 11
// speedup vs baseline: 1.7497x; 1.7497x over previous
#include <cuda_runtime.h>

#define BB 32
#define TT 128
#define DD 512
#define UU 512
#define G4 2048
#define NCTA 128
#define NTHR 512

// ---------------- scratch (device globals: allocation-free) ----------------
__device__ float g_attx[BB*TT*UU];      // 8 MB   tanh(x@W_att + b_att)
__device__ float g_xk  [BB*TT*G4];      // 32 MB  x@kernel + bias
__device__ float g_h[2][BB*UU];         // double-buffered hidden state
__device__ float g_c   [BB*UU];
__device__ float g_hU  [BB*UU];
__device__ float g_z   [BB*DD];
__device__ float g_sc  [BB*TT];
__device__ unsigned g_gcnt, g_ggen;     // grid barrier
__device__ unsigned g_lcnt[BB], g_lgen[BB];  // per-batch 4-CTA barriers

__device__ __forceinline__ float my_tanh(float x) {
    x = fminf(fmaxf(x, -15.f), 15.f);
    float e = __expf(2.f * x);
    return __fdividef(e - 1.f, e + 1.f);
}
__device__ __forceinline__ float hsig(float x) {
    return fminf(fmaxf(0.2f * x + 0.5f, 0.f), 1.f);
}

// Software barrier. Safe: all participating CTAs are co-resident (1 CTA/SM,
// 128 <= 148). __threadfence (gpu scope) both publishes prior writes and
// invalidates L1 (CCTL.IVALL) so post-barrier reads see peer CTA data.
__device__ __forceinline__ void bar_sync(unsigned* cnt, unsigned* gen, unsigned n) {
    __syncthreads();
    if (threadIdx.x == 0) {
        __threadfence();
        unsigned my = *(volatile unsigned*)gen;
        if (atomicAdd(cnt, 1u) == n - 1u) {
            *cnt = 0u;
            __threadfence();
            atomicAdd(gen, 1u);
        } else {
            while (*(volatile unsigned*)gen == my) { }
        }
        __threadfence();
    }
    __syncthreads();
}

// ---------------- precompute: one SGEMM over virtual N = 2048 + 512 --------
// n<2048 -> g_xk = X@kernel + bias ; n>=2048 -> g_attx = tanh(X@W_att + ab)
__global__ void __launch_bounds__(256) k_pre(
        const float* __restrict__ x, const float* __restrict__ Wk,
        const float* __restrict__ Wa, const float* __restrict__ bias,
        const float* __restrict__ ab) {
    __shared__ float As[16][132];
    __shared__ float Bs[16][64];
    int m0 = blockIdx.y * 128;
    int n0 = blockIdx.x * 64;
    bool isK = (n0 < G4);
    const float* Wm = isK ? Wk : Wa;
    int ldw = isK ? G4 : UU;
    int nc0 = isK ? n0 : (n0 - G4);
    int tid = threadIdx.x;
    int tm = (tid >> 4) * 8;
    int tn = (tid & 15) * 4;
    float acc[8][4];
    #pragma unroll
    for (int i = 0; i < 8; i++)
        #pragma unroll
        for (int j = 0; j < 4; j++) acc[i][j] = 0.f;

    for (int k0 = 0; k0 < DD; k0 += 16) {
        #pragma unroll
        for (int i = 0; i < 2; i++) {
            int idx = tid + i * 256;
            int row = idx >> 2;
            int c4  = (idx & 3) * 4;
            float4 v = *(const float4*)(x + (size_t)(m0 + row) * DD + k0 + c4);
            As[c4+0][row] = v.x; As[c4+1][row] = v.y;
            As[c4+2][row] = v.z; As[c4+3][row] = v.w;
        }
        {
            int row = tid >> 4;
            int c4  = (tid & 15) * 4;
            *(float4*)&Bs[row][c4] =
                *(const float4*)(Wm + (size_t)(k0 + row) * ldw + nc0 + c4);
        }
        __syncthreads();
        #pragma unroll
        for (int kk = 0; kk < 16; kk++) {
            float4 a0 = *(float4*)&As[kk][tm];
            float4 a1 = *(float4*)&As[kk][tm + 4];
            float4 bv = *(float4*)&Bs[kk][tn];
            float am[8] = {a0.x,a0.y,a0.z,a0.w,a1.x,a1.y,a1.z,a1.w};
            float bn[4] = {bv.x,bv.y,bv.z,bv.w};
            #pragma unroll
            for (int i = 0; i < 8; i++)
                #pragma unroll
                for (int j = 0; j < 4; j++)
                    acc[i][j] = fmaf(am[i], bn[j], acc[i][j]);
        }
        __syncthreads();
    }
    const float* bvec = isK ? bias : ab;
    float bj[4];
    #pragma unroll
    for (int j = 0; j < 4; j++) bj[j] = bvec[nc0 + tn + j];
    #pragma unroll
    for (int i = 0; i < 8; i++) {
        int m = m0 + tm + i;
        if (isK) {
            float* dst = g_xk + (size_t)m * G4 + nc0 + tn;
            #pragma unroll
            for (int j = 0; j < 4; j++) dst[j] = acc[i][j] + bj[j];
        } else {
            float* dst = g_attx + (size_t)m * UU + nc0 + tn;
            #pragma unroll
            for (int j = 0; j < 4; j++) dst[j] = my_tanh(acc[i][j] + bj[j]);
        }
    }
}

// ---------------- persistent scan kernel -----------------------------------
// 128 CTAs x 512 threads, 1 CTA/SM. Per step:
//   P1: hU = h @ Ua (CTA owns 4 u-cols)            [grid bar]
//   P2: scores (tanh addition formula) -> local 4-CTA bar -> softmax+z
//                                                   [grid bar]
//   P3: gates = xk + [h;z] @ [R;A] (W in persistent smem), LSTM pointwise
//                                                   [grid bar]
// smem floats: W_s[16384] | V_s[512] | scratch[34816] | gate_s[512]
__global__ void __launch_bounds__(NTHR, 1) k_scan(
        const float* __restrict__ x,  const float* __restrict__ R,
        const float* __restrict__ A,  const float* __restrict__ Ua,
        const float* __restrict__ V,  float* __restrict__ out) {
    extern __shared__ float sm[];
    float* W_s    = sm;
    float* V_s    = sm + 16384;
    float* S      = sm + 16896;
    float* gate_s = sm + 51712;

    const int bid = blockIdx.x;
    const int tid = threadIdx.x;
    const int u0  = bid * 4;
    const int wid = tid >> 5, lane = tid & 31;
    const int pb  = bid >> 2, pr = bid & 3;   // P2 role: batch, t-chunk

    // ---- one-time init: zero state, stage weights ----
    if (tid < 128) {
        int i = bid * 128 + tid;
        g_h[0][i] = 0.f; g_h[1][i] = 0.f; g_c[i] = 0.f;
    }
    #pragma unroll 4
    for (int i = 0; i < 32; i++) {
        int idx = tid + i * 512;
        int k = idx >> 4, ci = idx & 15;
        int col = ((ci >> 2) << 9) + u0 + (ci & 3);
        W_s[idx] = (k < 512) ? R[(size_t)k * G4 + col]
                             : A[(size_t)(k - 512) * G4 + col];
    }
    V_s[tid] = V[tid];
    __threadfence();
    bar_sync(&g_gcnt, &g_ggen, NCTA);

    for (int t = 0; t < TT; t++) {
        int par = t & 1;
        const float* hsrc = g_h[par];

        // ================= P1: hU cols [u0, u0+4) =================
        {
            float* h_s  = S;            // [32][516]
            float* Ua_s = S + 16512;    // [512][4]
            float* hred = S + 18560;    // [512]
            #pragma unroll 8
            for (int i = 0; i < 32; i++) {
                int idx = tid + i * 512;
                h_s[(idx >> 9) * 516 + (idx & 511)] = hsrc[idx];
            }
            #pragma unroll
            for (int i = 0; i < 4; i++) {
                int idx = tid + i * 512;
                Ua_s[idx] = Ua[(size_t)(idx >> 2) * UU + u0 + (idx & 3)];
            }
            __syncthreads();
            int ks = tid >> 7;          // warp-uniform k slice
            int b  = (tid >> 2) & 31;
            int c  = tid & 3;
            const float* hp = &h_s[b * 516 + ks * 128];
            const float* up = &Ua_s[(ks * 128) * 4 + c];
            float acc = 0.f;
            #pragma unroll 8
            for (int k = 0; k < 128; k++)
                acc = fmaf(hp[k], up[k * 4], acc);
            hred[tid] = acc;
            __syncthreads();
            if (tid < 128) {
                float v = hred[tid] + hred[tid+128] + hred[tid+256] + hred[tid+384];
                g_hU[(tid >> 2) * UU + u0 + (tid & 3)] = v;
            }
        }
        __threadfence();
        bar_sync(&g_gcnt, &g_ggen, NCTA);

        // ====== P2: scores (addition formula) + softmax + z for batch pb ======
        {
            float2* pair_s = (float2*)S;     // 512 x (ts, V)
            float*  al_s   = S + 1024;       // 128 alpha
            float*  zred   = S + 1152;       // 512
            float*  wr     = S + 1664;       // 8
            {
                float hu = g_hU[pb * UU + tid];
                pair_s[tid] = make_float2(my_tanh(hu), V_s[tid]);
            }
            __syncthreads();
            // scores: warp handles 2 timesteps. 1 MUFU per element.
            int t0 = pr * 32 + wid * 2;
            const float* ax0 = g_attx + ((size_t)(pb * TT + t0)) * UU;
            const float* ax1 = ax0 + UU;
            float a0 = 0.f, a1 = 0.f;
            #pragma unroll
            for (int i = 0; i < 16; i++) {
                int u = i * 32 + lane;
                float2 pv = pair_s[u];
                float ta0 = ax0[u], ta1 = ax1[u];
                float e0 = __fdividef(ta0 + pv.x, fmaf(ta0, pv.x, 1.f));
                float e1 = __fdividef(ta1 + pv.x, fmaf(ta1, pv.x, 1.f));
                a0 = fmaf(e0, pv.y, a0);
                a1 = fmaf(e1, pv.y, a1);
            }
            #pragma unroll
            for (int off = 16; off; off >>= 1) {
                a0 += __shfl_xor_sync(0xffffffffu, a0, off);
                a1 += __shfl_xor_sync(0xffffffffu, a1, off);
            }
            if (lane == 0) {
                g_sc[pb * TT + t0]     = a0;
                g_sc[pb * TT + t0 + 1] = a1;
            }
            __threadfence();
            bar_sync(&g_lcnt[pb], &g_lgen[pb], 4u);   // 4 CTAs of batch pb

            // softmax over T=128 (redundant x4, cheap)
            float sv = -1e30f;
            if (tid < 128) sv = g_sc[pb * TT + tid];
            float mv = sv;
            #pragma unroll
            for (int off = 16; off; off >>= 1)
                mv = fmaxf(mv, __shfl_xor_sync(0xffffffffu, mv, off));
            if (lane == 0 && wid < 4) wr[wid] = mv;
            __syncthreads();
            float mx = fmaxf(fmaxf(wr[0], wr[1]), fmaxf(wr[2], wr[3]));
            float e = (tid < 128) ? __expf(sv - mx) : 0.f;
            float es = e;
            #pragma unroll
            for (int off = 16; off; off >>= 1)
                es += __shfl_xor_sync(0xffffffffu, es, off);
            if (lane == 0 && wid < 4) wr[4 + wid] = es;
            __syncthreads();
            float tot = wr[4] + wr[5] + wr[6] + wr[7];
            if (tid < 128) al_s[tid] = e * __fdividef(1.f, tot);
            __syncthreads();

            // z chunk: d in [pr*128, pr*128+128)
            int dl = tid & 127, ts4 = tid >> 7;
            const float* xb = x + ((size_t)pb * TT + ts4 * 32) * DD + pr * 128 + dl;
            float zp = 0.f;
            #pragma unroll 8
            for (int tt = 0; tt < 32; tt++)
                zp = fmaf(al_s[ts4 * 32 + tt], xb[(size_t)tt * DD], zp);
            zred[tid] = zp;
            __syncthreads();
            if (tid < 128) {
                float z = zred[tid] + zred[tid+128] + zred[tid+256] + zred[tid+384];
                g_z[pb * DD + pr * 128 + tid] = z;
            }
        }
        __threadfence();
        bar_sync(&g_gcnt, &g_ggen, NCTA);

        // ================= P3: gates + LSTM pointwise =================
        {
            float* hz = S;   // [1024][34]
            float xkv;
            {
                int b = tid >> 4, ci = tid & 15;
                int col = ((ci >> 2) << 9) + u0 + (ci & 3);
                xkv = g_xk[((size_t)(b * TT) + t) * G4 + col];
            }
            #pragma unroll 8
            for (int i = 0; i < 32; i++) {
                int idx = tid + i * 512;
                hz[(idx & 511) * 34 + (idx >> 9)] = hsrc[idx];
            }
            #pragma unroll 8
            for (int i = 0; i < 32; i++) {
                int idx = tid + i * 512;
                hz[((idx & 511) + 512) * 34 + (idx >> 9)] = g_z[idx];
            }
            __syncthreads();

            int ks  = tid >> 6;           // warp-uniform (2 warps per slice)
            int bq  = (tid >> 2) & 15;    // 2 batches
            int ciq = tid & 3;            // 4 gate cols
            float acc00=0,acc01=0,acc02=0,acc03=0;
            float acc10=0,acc11=0,acc12=0,acc13=0;
            const float* hp = &hz[(ks * 128) * 34 + bq * 2];
            const float* wp = &W_s[(ks * 128) * 16 + ciq * 4];
            #pragma unroll 4
            for (int k = 0; k < 128; k++) {
                float2 hv = *(const float2*)&hp[k * 34];
                float4 wv = *(const float4*)&wp[k * 16];
                acc00 = fmaf(hv.x, wv.x, acc00);
                acc01 = fmaf(hv.x, wv.y, acc01);
                acc02 = fmaf(hv.x, wv.z, acc02);
                acc03 = fmaf(hv.x, wv.w, acc03);
                acc10 = fmaf(hv.y, wv.x, acc10);
                acc11 = fmaf(hv.y, wv.y, acc11);
                acc12 = fmaf(hv.y, wv.z, acc12);
                acc13 = fmaf(hv.y, wv.w, acc13);
            }
            __syncthreads();
            float* red = S;  // reuse front of scratch: [8][512]
            {
                int base0 = ks * 512 + (bq * 2)     * 16 + ciq * 4;
                int base1 = ks * 512 + (bq * 2 + 1) * 16 + ciq * 4;
                red[base0+0]=acc00; red[base0+1]=acc01;
                red[base0+2]=acc02; red[base0+3]=acc03;
                red[base1+0]=acc10; red[base1+1]=acc11;
                red[base1+2]=acc12; red[base1+3]=acc13;
            }
            __syncthreads();
            {
                float g = xkv;
                #pragma unroll
                for (int s2 = 0; s2 < 8; s2++) g += red[s2 * 512 + tid];
                gate_s[tid] = g;
            }
            __syncthreads();
            if (tid < 128) {
                int b = tid >> 2, jj = tid & 3;
                float gi = hsig(gate_s[b * 16 + 0  + jj]);
                float gf = hsig(gate_s[b * 16 + 4  + jj]);
                float gg = my_tanh(gate_s[b * 16 + 8  + jj]);
                float go = hsig(gate_s[b * 16 + 12 + jj]);
                int idx = b * UU + u0 + jj;
                float cn = gf * g_c[idx] + gi * gg;
                g_c[idx] = cn;
                float hn = go * my_tanh(cn);
                g_h[par ^ 1][idx] = hn;
                out[((size_t)b * TT + t) * UU + u0 + jj] = hn;
            }
        }
        __threadfence();
        bar_sync(&g_gcnt, &g_ggen, NCTA);
    }
}

// ---------------------------------------------------------------------------
extern "C" void kernel_launch(void* const* d_in, const int* in_sizes, int n_in,
                              void* d_out, int out_size) {
    const float* x    = (const float*)d_in[0];
    const float* Wk   = (const float*)d_in[1];  // kernel (D,4U)
    const float* R    = (const float*)d_in[2];  // recurrent_kernel (U,4U)
    const float* A    = (const float*)d_in[3];  // attention_kernel (D,4U)
    const float* Wa   = (const float*)d_in[4];  // attention_W (D,U)
    const float* Ua   = (const float*)d_in[5];  // attention_U (U,U)
    const float* V    = (const float*)d_in[6];  // attention_V (U,1)
    const float* bias = (const float*)d_in[7];  // (4U)
    const float* ab   = (const float*)d_in[8];  // attention_b (U)
    float* out = (float*)d_out;

    const int SCAN_SMEM = 52224 * 4;  // 208896 B
    cudaFuncSetAttribute(k_scan, cudaFuncAttributeMaxDynamicSharedMemorySize,
                         SCAN_SMEM);

    k_pre<<<dim3(40, 32), 256>>>(x, Wk, Wa, bias, ab);
    k_scan<<<NCTA, NTHR, SCAN_SMEM>>>(x, R, A, Ua, V, out);
}

// round 12
// speedup vs baseline: 1.9392x; 1.1083x over previous
#include <cuda_runtime.h>

#define BB 32
#define TT 128
#define DD 512
#define UU 512
#define G4 2048
#define NCTA 128
#define NTHR 512

// ---------------- scratch (device globals: allocation-free) ----------------
__device__ float g_attx[BB*TT*UU];      // 8 MB   tanh(x@W_att + b_att)
__device__ float g_xk  [BB*TT*G4];      // 32 MB  x@kernel + bias
__device__ float g_h[2][BB*UU];         // double-buffered hidden state
__device__ float g_c   [BB*UU];
__device__ float g_hU  [BB*UU];         // stores tanh(h @ Ua)
__device__ float g_z   [BB*DD];
__device__ float g_sc  [BB*TT];
__device__ unsigned g_gcnt, g_ggen;          // grid barrier
__device__ unsigned g_lcnt[BB], g_lgen[BB];  // per-batch 4-CTA barriers

__device__ __forceinline__ float my_tanh(float x) {
    x = fminf(fmaxf(x, -15.f), 15.f);
    float e = __expf(2.f * x);
    return __fdividef(e - 1.f, e + 1.f);
}
__device__ __forceinline__ float hsig(float x) {
    return fminf(fmaxf(0.2f * x + 0.5f, 0.f), 1.f);
}

// Software barrier. Safe: all participating CTAs co-resident (1 CTA/SM,
// 128 <= 148 SMs). __threadfence (gpu scope) publishes prior writes and
// invalidates L1 so post-barrier reads see peer-CTA data.
__device__ __forceinline__ void bar_sync(unsigned* cnt, unsigned* gen, unsigned n) {
    __syncthreads();
    if (threadIdx.x == 0) {
        __threadfence();
        unsigned my = *(volatile unsigned*)gen;
        if (atomicAdd(cnt, 1u) == n - 1u) {
            *cnt = 0u;
            __threadfence();
            atomicAdd(gen, 1u);
        } else {
            while (*(volatile unsigned*)gen == my) { }
        }
        __threadfence();
    }
    __syncthreads();
}

// ---------------- precompute: one SGEMM over virtual N = 2048 + 512 --------
// n<2048 -> g_xk = X@kernel + bias ; n>=2048 -> g_attx = tanh(X@W_att + ab)
__global__ void __launch_bounds__(256) k_pre(
        const float* __restrict__ x, const float* __restrict__ Wk,
        const float* __restrict__ Wa, const float* __restrict__ bias,
        const float* __restrict__ ab) {
    __shared__ float As[16][132];
    __shared__ float Bs[16][64];
    int m0 = blockIdx.y * 128;
    int n0 = blockIdx.x * 64;
    bool isK = (n0 < G4);
    const float* Wm = isK ? Wk : Wa;
    int ldw = isK ? G4 : UU;
    int nc0 = isK ? n0 : (n0 - G4);
    int tid = threadIdx.x;
    int tm = (tid >> 4) * 8;
    int tn = (tid & 15) * 4;
    float acc[8][4];
    #pragma unroll
    for (int i = 0; i < 8; i++)
        #pragma unroll
        for (int j = 0; j < 4; j++) acc[i][j] = 0.f;

    for (int k0 = 0; k0 < DD; k0 += 16) {
        #pragma unroll
        for (int i = 0; i < 2; i++) {
            int idx = tid + i * 256;
            int row = idx >> 2;
            int c4  = (idx & 3) * 4;
            float4 v = *(const float4*)(x + (size_t)(m0 + row) * DD + k0 + c4);
            As[c4+0][row] = v.x; As[c4+1][row] = v.y;
            As[c4+2][row] = v.z; As[c4+3][row] = v.w;
        }
        {
            int row = tid >> 4;
            int c4  = (tid & 15) * 4;
            *(float4*)&Bs[row][c4] =
                *(const float4*)(Wm + (size_t)(k0 + row) * ldw + nc0 + c4);
        }
        __syncthreads();
        #pragma unroll
        for (int kk = 0; kk < 16; kk++) {
            float4 a0 = *(float4*)&As[kk][tm];
            float4 a1 = *(float4*)&As[kk][tm + 4];
            float4 bv = *(float4*)&Bs[kk][tn];
            float am[8] = {a0.x,a0.y,a0.z,a0.w,a1.x,a1.y,a1.z,a1.w};
            float bn[4] = {bv.x,bv.y,bv.z,bv.w};
            #pragma unroll
            for (int i = 0; i < 8; i++)
                #pragma unroll
                for (int j = 0; j < 4; j++)
                    acc[i][j] = fmaf(am[i], bn[j], acc[i][j]);
        }
        __syncthreads();
    }
    const float* bvec = isK ? bias : ab;
    float bj[4];
    #pragma unroll
    for (int j = 0; j < 4; j++) bj[j] = bvec[nc0 + tn + j];
    #pragma unroll
    for (int i = 0; i < 8; i++) {
        int m = m0 + tm + i;
        if (isK) {
            float* dst = g_xk + (size_t)m * G4 + nc0 + tn;
            #pragma unroll
            for (int j = 0; j < 4; j++) dst[j] = acc[i][j] + bj[j];
        } else {
            float* dst = g_attx + (size_t)m * UU + nc0 + tn;
            #pragma unroll
            for (int j = 0; j < 4; j++) dst[j] = my_tanh(acc[i][j] + bj[j]);
        }
    }
}

// ---------------- persistent scan kernel (2 phases per step) ---------------
// 128 CTAs x 512 thr, 1 CTA/SM.
// Phase A (CTA = (pb,pr)): hU slice (direct Ua read) -> lbar -> scores
//                          (tanh addition formula) -> lbar -> softmax + z
// [grid bar]
// Phase B (CTA = u-tile):  gates = xk + [h;z]@[R;A] (W persistent in smem,
//                          hz in XOR-swizzled smem), LSTM pointwise
// [grid bar]
// smem floats: W_s[16384] | V_s[512] | hz[32768] | gate_s[512]  (~200.7 KB)
__global__ void __launch_bounds__(NTHR, 1) k_scan(
        const float* __restrict__ x,  const float* __restrict__ R,
        const float* __restrict__ A,  const float* __restrict__ Ua,
        const float* __restrict__ V,  float* __restrict__ out) {
    extern __shared__ float sm[];
    float* W_s    = sm;
    float* V_s    = sm + 16384;
    float* hz     = sm + 16896;     // 32768 floats; Phase A scratch aliases it
    float* gate_s = sm + 49664;

    const int bid = blockIdx.x;
    const int tid = threadIdx.x;
    const int u0  = bid * 4;                  // Phase B u-tile
    const int wid = tid >> 5, lane = tid & 31;
    const int pb  = bid >> 2, pr = bid & 3;   // Phase A role

    // Phase A scratch layout inside hz
    float*  h_s    = hz;                      // 512
    float4* hred4  = (float4*)(hz + 512);     // 16 x 32 float4
    float2* pair_s = (float2*)(hz + 2560);    // 512 float2
    float*  al_s   = hz + 3584;               // 128
    float4* zred4  = (float4*)(hz + 3712);    // 16 x 32 float4
    float*  wr     = hz + 5760;               // 8

    // ---- one-time init: zero state, stage weights ----
    if (tid < 128) {
        int i = bid * 128 + tid;
        g_h[0][i] = 0.f; g_h[1][i] = 0.f; g_c[i] = 0.f;
    }
    #pragma unroll 4
    for (int i = 0; i < 32; i++) {
        int idx = tid + i * 512;
        int k = idx >> 4, ci = idx & 15;
        int col = ((ci >> 2) << 9) + u0 + (ci & 3);
        W_s[idx] = (k < 512) ? R[(size_t)k * G4 + col]
                             : A[(size_t)(k - 512) * G4 + col];
    }
    V_s[tid] = V[tid];
    bar_sync(&g_gcnt, &g_ggen, NCTA);

    for (int t = 0; t < TT; t++) {
        int par = t & 1;
        const float* hsrc = g_h[par];

        // ========================= Phase A =========================
        // A1: hU slice: tanh( h[pb,:] @ Ua[:, pr*128 .. pr*128+128) )
        h_s[tid] = hsrc[pb * UU + tid];
        __syncthreads();
        {
            int c4 = tid & 31;            // float4 col in 128-col slice
            int ks = tid >> 5;            // 0..15, 32 k each
            const float4* up = (const float4*)Ua
                               + (size_t)(ks * 32) * 128 + pr * 32 + c4;
            float4 a = make_float4(0.f, 0.f, 0.f, 0.f);
            #pragma unroll 8
            for (int j = 0; j < 32; j++) {
                float hv = h_s[ks * 32 + j];
                float4 w = up[(size_t)j * 128];
                a.x = fmaf(hv, w.x, a.x); a.y = fmaf(hv, w.y, a.y);
                a.z = fmaf(hv, w.z, a.z); a.w = fmaf(hv, w.w, a.w);
            }
            hred4[ks * 32 + c4] = a;
        }
        __syncthreads();
        if (tid < 32) {
            float4 s = hred4[tid];
            #pragma unroll
            for (int k = 1; k < 16; k++) {
                float4 v = hred4[k * 32 + tid];
                s.x += v.x; s.y += v.y; s.z += v.z; s.w += v.w;
            }
            s.x = my_tanh(s.x); s.y = my_tanh(s.y);
            s.z = my_tanh(s.z); s.w = my_tanh(s.w);
            ((float4*)(g_hU + pb * UU + pr * 128))[tid] = s;
        }
        bar_sync(&g_lcnt[pb], &g_lgen[pb], 4u);

        // A2: scores for t-chunk [pr*32, pr*32+32), addition formula (1 MUFU/elem)
        pair_s[tid] = make_float2(g_hU[pb * UU + tid], V_s[tid]);
        __syncthreads();
        {
            int t0 = pr * 32 + wid * 2;
            const float4* ax0 = (const float4*)(g_attx + (size_t)(pb * TT + t0) * UU);
            const float4* ax1 = ax0 + 128;
            float a0 = 0.f, a1 = 0.f;
            #pragma unroll
            for (int i = 0; i < 4; i++) {
                int u4 = i * 32 + lane;
                float4 t0v = ax0[u4], t1v = ax1[u4];
                float2 p0 = pair_s[u4*4+0], p1 = pair_s[u4*4+1];
                float2 p2 = pair_s[u4*4+2], p3 = pair_s[u4*4+3];
                a0 = fmaf(__fdividef(t0v.x + p0.x, fmaf(t0v.x, p0.x, 1.f)), p0.y, a0);
                a0 = fmaf(__fdividef(t0v.y + p1.x, fmaf(t0v.y, p1.x, 1.f)), p1.y, a0);
                a0 = fmaf(__fdividef(t0v.z + p2.x, fmaf(t0v.z, p2.x, 1.f)), p2.y, a0);
                a0 = fmaf(__fdividef(t0v.w + p3.x, fmaf(t0v.w, p3.x, 1.f)), p3.y, a0);
                a1 = fmaf(__fdividef(t1v.x + p0.x, fmaf(t1v.x, p0.x, 1.f)), p0.y, a1);
                a1 = fmaf(__fdividef(t1v.y + p1.x, fmaf(t1v.y, p1.x, 1.f)), p1.y, a1);
                a1 = fmaf(__fdividef(t1v.z + p2.x, fmaf(t1v.z, p2.x, 1.f)), p2.y, a1);
                a1 = fmaf(__fdividef(t1v.w + p3.x, fmaf(t1v.w, p3.x, 1.f)), p3.y, a1);
            }
            #pragma unroll
            for (int off = 16; off; off >>= 1) {
                a0 += __shfl_xor_sync(0xffffffffu, a0, off);
                a1 += __shfl_xor_sync(0xffffffffu, a1, off);
            }
            if (lane == 0) {
                g_sc[pb * TT + t0]     = a0;
                g_sc[pb * TT + t0 + 1] = a1;
            }
        }
        bar_sync(&g_lcnt[pb], &g_lgen[pb], 4u);

        // A3: softmax over T (redundant x4) + z chunk [pr*128, pr*128+128)
        {
            float sv = -1e30f;
            if (tid < 128) sv = g_sc[pb * TT + tid];
            float mv = sv;
            #pragma unroll
            for (int off = 16; off; off >>= 1)
                mv = fmaxf(mv, __shfl_xor_sync(0xffffffffu, mv, off));
            if (lane == 0 && wid < 4) wr[wid] = mv;
            __syncthreads();
            float mx = fmaxf(fmaxf(wr[0], wr[1]), fmaxf(wr[2], wr[3]));
            float e = (tid < 128) ? __expf(sv - mx) : 0.f;
            float es = e;
            #pragma unroll
            for (int off = 16; off; off >>= 1)
                es += __shfl_xor_sync(0xffffffffu, es, off);
            if (lane == 0 && wid < 4) wr[4 + wid] = es;
            __syncthreads();
            float tot = wr[4] + wr[5] + wr[6] + wr[7];
            if (tid < 128) al_s[tid] = e * __fdividef(1.f, tot);
            __syncthreads();

            int c4 = tid & 31;            // float4 d-col in 128-d slice
            int tg = tid >> 5;            // 0..15 -> 8 timesteps each
            const float4* x4 = (const float4*)(x + (size_t)pb * TT * DD + pr * 128);
            float4 zp = make_float4(0.f, 0.f, 0.f, 0.f);
            #pragma unroll
            for (int j = 0; j < 8; j++) {
                int ts = tg * 8 + j;
                float av = al_s[ts];
                float4 xv = x4[(size_t)ts * 128 + c4];
                zp.x = fmaf(av, xv.x, zp.x); zp.y = fmaf(av, xv.y, zp.y);
                zp.z = fmaf(av, xv.z, zp.z); zp.w = fmaf(av, xv.w, zp.w);
            }
            zred4[tg * 32 + c4] = zp;
            __syncthreads();
            if (tid < 32) {
                float4 s = zred4[tid];
                #pragma unroll
                for (int k = 1; k < 16; k++) {
                    float4 v = zred4[k * 32 + tid];
                    s.x += v.x; s.y += v.y; s.z += v.z; s.w += v.w;
                }
                ((float4*)(g_z + pb * DD + pr * 128))[tid] = s;
            }
        }
        bar_sync(&g_gcnt, &g_ggen, NCTA);

        // ========================= Phase B =========================
        {
            float xkv;
            {
                int b = tid >> 4, ci = tid & 15;
                int col = ((ci >> 2) << 9) + u0 + (ci & 3);
                xkv = g_xk[((size_t)(b * TT) + t) * G4 + col];
            }
            // stage h,z: [b][k] with XOR swizzle, float4 throughout
            const float4* h4 = (const float4*)hsrc;
            const float4* z4 = (const float4*)g_z;
            #pragma unroll
            for (int i = 0; i < 8; i++) {
                int idx4 = tid + i * 512;
                int b  = idx4 >> 7;
                int k0 = (idx4 & 127) << 2;
                float4 v = h4[idx4];
                *(float4*)&hz[b * 1024 + (k0 ^ ((b & 7) << 2))] = v;
            }
            #pragma unroll
            for (int i = 0; i < 8; i++) {
                int idx4 = tid + i * 512;
                int b  = idx4 >> 7;
                int k0 = ((idx4 & 127) << 2) + 512;
                float4 v = z4[idx4];
                *(float4*)&hz[b * 1024 + (k0 ^ ((b & 7) << 2))] = v;
            }
            __syncthreads();

            int ks  = tid >> 6;           // 0..7 (warp-uniform)
            int bq  = (tid >> 2) & 15;
            int ciq = tid & 3;
            int b0 = bq * 2, b1 = b0 + 1;
            int m0 = (b0 & 7) << 2, m1 = (b1 & 7) << 2;
            const float* hp0 = &hz[b0 * 1024];
            const float* hp1 = &hz[b1 * 1024];
            const float* wp  = &W_s[ciq * 4];
            float a00=0,a01=0,a02=0,a03=0, a10=0,a11=0,a12=0,a13=0;
            int kb = ks * 128;
            #pragma unroll 4
            for (int k2 = 0; k2 < 64; k2++) {
                int k = kb + k2 * 2;
                float2 hv0 = *(const float2*)&hp0[k ^ m0];
                float2 hv1 = *(const float2*)&hp1[k ^ m1];
                float4 w0 = *(const float4*)&wp[k * 16];
                float4 w1 = *(const float4*)&wp[(k + 1) * 16];
                a00 = fmaf(hv0.x, w0.x, a00); a01 = fmaf(hv0.x, w0.y, a01);
                a02 = fmaf(hv0.x, w0.z, a02); a03 = fmaf(hv0.x, w0.w, a03);
                a10 = fmaf(hv1.x, w0.x, a10); a11 = fmaf(hv1.x, w0.y, a11);
                a12 = fmaf(hv1.x, w0.z, a12); a13 = fmaf(hv1.x, w0.w, a13);
                a00 = fmaf(hv0.y, w1.x, a00); a01 = fmaf(hv0.y, w1.y, a01);
                a02 = fmaf(hv0.y, w1.z, a02); a03 = fmaf(hv0.y, w1.w, a03);
                a10 = fmaf(hv1.y, w1.x, a10); a11 = fmaf(hv1.y, w1.y, a11);
                a12 = fmaf(hv1.y, w1.z, a12); a13 = fmaf(hv1.y, w1.w, a13);
            }
            __syncthreads();
            float* red = hz;              // reuse: 8 x 512 partials
            *(float4*)&red[ks * 512 + b0 * 16 + ciq * 4] =
                make_float4(a00, a01, a02, a03);
            *(float4*)&red[ks * 512 + b1 * 16 + ciq * 4] =
                make_float4(a10, a11, a12, a13);
            __syncthreads();
            {
                float g = xkv;
                #pragma unroll
                for (int s2 = 0; s2 < 8; s2++) g += red[s2 * 512 + tid];
                gate_s[tid] = g;
            }
            __syncthreads();
            if (tid < 128) {
                int b = tid >> 2, jj = tid & 3;
                float gi = hsig(gate_s[b * 16 + 0  + jj]);
                float gf = hsig(gate_s[b * 16 + 4  + jj]);
                float gg = my_tanh(gate_s[b * 16 + 8  + jj]);
                float go = hsig(gate_s[b * 16 + 12 + jj]);
                int idx = b * UU + u0 + jj;
                float cn = gf * g_c[idx] + gi * gg;
                g_c[idx] = cn;
                float hn = go * my_tanh(cn);
                g_h[par ^ 1][idx] = hn;
                out[((size_t)b * TT + t) * UU + u0 + jj] = hn;
            }
        }
        bar_sync(&g_gcnt, &g_ggen, NCTA);
    }
}

// ---------------------------------------------------------------------------
extern "C" void kernel_launch(void* const* d_in, const int* in_sizes, int n_in,
                              void* d_out, int out_size) {
    const float* x    = (const float*)d_in[0];
    const float* Wk   = (const float*)d_in[1];  // kernel (D,4U)
    const float* R    = (const float*)d_in[2];  // recurrent_kernel (U,4U)
    const float* A    = (const float*)d_in[3];  // attention_kernel (D,4U)
    const float* Wa   = (const float*)d_in[4];  // attention_W (D,U)
    const float* Ua   = (const float*)d_in[5];  // attention_U (U,U)
    const float* V    = (const float*)d_in[6];  // attention_V (U,1)
    const float* bias = (const float*)d_in[7];  // (4U)
    const float* ab   = (const float*)d_in[8];  // attention_b (U)
    float* out = (float*)d_out;

    const int SCAN_SMEM = 50176 * 4;  // 200704 B
    cudaFuncSetAttribute(k_scan, cudaFuncAttributeMaxDynamicSharedMemorySize,
                         SCAN_SMEM);

    k_pre<<<dim3(40, 32), 256>>>(x, Wk, Wa, bias, ab);
    k_scan<<<NCTA, NTHR, SCAN_SMEM>>>(x, R, A, Ua, V, out);
}